// round 16
// baseline (speedup 1.0000x reference)
#include <cuda_runtime.h>
#include <cuda_bf16.h>
#include <math.h>
#include <stdint.h>

#define Bq 64
#define Hd 1024
#define Tt 128
#define NSTEP 127
#define Cc 50000
#define GRID 256
#define TM 64
#define TN 64
#define KCH 32
#define ASf 36     // fp32 final-gemm A smem stride
#define WSf 34     // fp32 final-gemm W smem stride
#define AS 136     // bf16 smem row stride (all phases)
#define SMEMB (4 * 64 * AS * 2)    // 69,632 B
#define NLEAF 32
#define LSTR 64    // leaf counter stride (uints) = 256 B

// Scratch (no cudaMalloc allowed)
__device__ float g_h[2][Bq * Hd];
__device__ float g_out1[Bq * Hd];
__device__ float g_out23[Bq * 2 * Hd];
__device__ float g_out45[Bq * 2 * Hd];
__device__ float g_part[256 * 4096];
__device__ float g_c[3];
__device__ unsigned g_tile_ctr[96];
__device__ unsigned g_leaf_cnt[NLEAF * LSTR];
__device__ unsigned g_root_cnt;
__device__ volatile unsigned g_root_gen;
__device__ unsigned g_exit_cnt;
// Pre-split recurrent weights: rows 0-6143 = Ws[0..5], rows 6144-7167 = W0. [row][1024] bf16.
__device__ __nv_bfloat16 g_Whi[7 * 1024 * 1024];
__device__ __nv_bfloat16 g_Wlo[7 * 1024 * 1024];

struct PArgs {
    const float* wv; const float* h; const int* bi;
    const float* W0; const float* b0;
    const float* Ws; const float* bs;
    const float* W_out; const float* b_out;
    const float* W_sum; const float* b_sum; const float* actions;
    float* out;
};

// ---------- helpers ----------
__device__ __forceinline__ unsigned long long ffma2(unsigned long long a,
                                                    unsigned long long b,
                                                    unsigned long long c) {
    unsigned long long d;
    asm("fma.rn.f32x2 %0, %1, %2, %3;" : "=l"(d) : "l"(a), "l"(b), "l"(c));
    return d;
}
__device__ __forceinline__ float unpack_sum(unsigned long long p) {
    float lo, hi;
    asm("mov.b64 {%0, %1}, %2;" : "=f"(lo), "=f"(hi) : "l"(p));
    return lo + hi;
}
__device__ __forceinline__ uint32_t su32(const void* p) {
    return (uint32_t)__cvta_generic_to_shared(p);
}
__device__ __forceinline__ void cp16(uint32_t saddr, const void* g) {
    asm volatile("cp.async.cg.shared.global [%0], [%1], 16;" :: "r"(saddr), "l"(g));
}
__device__ __forceinline__ void cp_commit() { asm volatile("cp.async.commit_group;"); }
__device__ __forceinline__ void cp_wait0()  { asm volatile("cp.async.wait_group 0;"); }
__device__ __forceinline__ void ldsm4(uint32_t* r, uint32_t addr) {
    asm volatile("ldmatrix.sync.aligned.m8n8.x4.shared.b16 {%0,%1,%2,%3}, [%4];"
                 : "=r"(r[0]), "=r"(r[1]), "=r"(r[2]), "=r"(r[3]) : "r"(addr));
}
__device__ __forceinline__ void mma_bf16(float* d, const uint32_t* a, uint32_t b0, uint32_t b1) {
    asm volatile("mma.sync.aligned.m16n8k16.row.col.f32.bf16.bf16.f32 "
                 "{%0,%1,%2,%3}, {%4,%5,%6,%7}, {%8,%9}, {%0,%1,%2,%3};"
                 : "+f"(d[0]), "+f"(d[1]), "+f"(d[2]), "+f"(d[3])
                 : "r"(a[0]), "r"(a[1]), "r"(a[2]), "r"(a[3]), "r"(b0), "r"(b1));
}
__device__ __forceinline__ void split4(__nv_bfloat16* hi, __nv_bfloat16* lo, float4 v) {
    __nv_bfloat16 h0 = __float2bfloat16_rn(v.x), h1 = __float2bfloat16_rn(v.y);
    __nv_bfloat16 h2 = __float2bfloat16_rn(v.z), h3 = __float2bfloat16_rn(v.w);
    __nv_bfloat16 l0 = __float2bfloat16_rn(v.x - __bfloat162float(h0));
    __nv_bfloat16 l1 = __float2bfloat16_rn(v.y - __bfloat162float(h1));
    __nv_bfloat16 l2 = __float2bfloat16_rn(v.z - __bfloat162float(h2));
    __nv_bfloat16 l3 = __float2bfloat16_rn(v.w - __bfloat162float(h3));
    __nv_bfloat162 a; a.x = h0; a.y = h1; *(__nv_bfloat162*)(hi)     = a;
    __nv_bfloat162 b; b.x = h2; b.y = h3; *(__nv_bfloat162*)(hi + 2) = b;
    __nv_bfloat162 c; c.x = l0; c.y = l1; *(__nv_bfloat162*)(lo)     = c;
    __nv_bfloat162 d; d.x = l2; d.y = l3; *(__nv_bfloat162*)(lo + 2) = d;
}

// ---------- sync ----------
// Tree-ARRIVAL barrier, single release line. Leaves: 32 distinct lines x 8 arrivals
// (parallel across LTS slices); root: 32 serialized arrivals. All waiters poll g_root_gen
// (single-line polling, same as the proven flat barrier). The leaf reset is FENCED before
// the root arrival so it is globally visible before the release that lets any CTA re-arrive.
// Safe: GRID=256 <= 148 SMs * 2 resident CTAs (launch_bounds(256,2)).
__device__ __forceinline__ void grid_barrier(unsigned target) {
    __syncthreads();
    if (threadIdx.x == 0) {
        __threadfence();
        const int leaf = (blockIdx.x & (NLEAF - 1)) * LSTR;
        unsigned prev = atomicAdd(&g_leaf_cnt[leaf], 1u);
        if (prev == (GRID / NLEAF) - 1u) {
            g_leaf_cnt[leaf] = 0u;
            __threadfence();                       // reset visible before root arrival
            unsigned rprev = atomicAdd(&g_root_cnt, 1u);
            if (rprev == NLEAF - 1u) {
                g_root_cnt = 0u;
                __threadfence();                   // reset visible before release
                g_root_gen = target;
            }
        }
        while (g_root_gen < target) { }
        __threadfence();
    }
    __syncthreads();
}
__device__ __forceinline__ void group_sync(unsigned* ctr, unsigned target) {
    __syncthreads();
    if (threadIdx.x == 0) {
        __threadfence();
        atomicAdd(ctr, 1u);
        while (*(volatile unsigned*)ctr < target) { }
        __threadfence();
    }
    __syncthreads();
}

// ---------- smem region accessors (bf16) ----------
__device__ __forceinline__ __nv_bfloat16* sm_Ahi(char* s) { return (__nv_bfloat16*)s; }
__device__ __forceinline__ __nv_bfloat16* sm_Alo(char* s) { return (__nv_bfloat16*)s + 64 * AS; }
__device__ __forceinline__ __nv_bfloat16* sm_Whi(char* s) { return (__nv_bfloat16*)s + 2 * 64 * AS; }
__device__ __forceinline__ __nv_bfloat16* sm_Wlo(char* s) { return (__nv_bfloat16*)s + 3 * 64 * AS; }

// Async W stage: pre-split bf16 rows -> smem via cp.async (completion via cp_wait0 later).
template<int KPER>
__device__ __forceinline__ void stage_W_async(
    const __nv_bfloat16* Whi, const __nv_bfloat16* Wlo, char* smem, int tid)
{
    __nv_bfloat16* sWhi = sm_Whi(smem);
    __nv_bfloat16* sWlo = sm_Wlo(smem);
    const int r0 = tid >> 3;
    const int t8 = tid & 7;
    #pragma unroll
    for (int rr = 0; rr < 2; rr++) {
        const int r = r0 + rr * 32;
        const __nv_bfloat16* sh = Whi + (size_t)r * Hd;
        const __nv_bfloat16* sl = Wlo + (size_t)r * Hd;
        if (KPER == 128) {
            const int k = t8 * 16;
            cp16(su32(&sWhi[r * AS + k]),     sh + k);
            cp16(su32(&sWhi[r * AS + k + 8]), sh + k + 8);
            cp16(su32(&sWlo[r * AS + k]),     sl + k);
            cp16(su32(&sWlo[r * AS + k + 8]), sl + k + 8);
        } else {   // KPER == 64
            const int k = t8 * 8;
            cp16(su32(&sWhi[r * AS + k]), sh + k);
            cp16(su32(&sWlo[r * AS + k]), sl + k);
        }
    }
    cp_commit();
}

// Stage A: load fp32, split to hi/lo bf16 in smem.
template<int KPER, bool GATHER>
__device__ __forceinline__ void stage_A(
    const float* A, int lda, int kbase,
    const float* wv, const int* idx, char* smem, int tid)
{
    __nv_bfloat16* sAhi = sm_Ahi(smem);
    __nv_bfloat16* sAlo = sm_Alo(smem);
    const int r0 = tid >> 3;
    const int kf = (tid & 7) * 4;
    #pragma unroll
    for (int rr = 0; rr < 2; rr++) {
        const int r = r0 + rr * 32;
        const float* arow;
        if (GATHER) arow = wv + (size_t)__ldg(idx + r * Tt) * Hd;
        else        arow = A + (size_t)r * lda;
        #pragma unroll
        for (int c = 0; c < KPER / 32; c++) {
            const int k = kf + 32 * c;
            float4 v = GATHER ? __ldg((const float4*)(arow + kbase + k))
                              : __ldcg((const float4*)(arow + kbase + k));
            split4(&sAhi[r * AS + k], &sAlo[r * AS + k], v);
        }
    }
}

// MMA compute on staged smem: acc += A @ W^T (bf16x3).
template<int KPER>
__device__ __forceinline__ void compute_mma(char* smem, int tid, float acc[4][4]) {
    __nv_bfloat16* sAhi = sm_Ahi(smem);
    __nv_bfloat16* sAlo = sm_Alo(smem);
    __nv_bfloat16* sWhi = sm_Whi(smem);
    __nv_bfloat16* sWlo = sm_Wlo(smem);

    const int lane = tid & 31;
    const int w    = tid >> 5;
    const int rw = (w >> 1) * 16;
    const int cw = (w & 1) * 32;
    const int rr8 = lane & 7;
    const int aRow = rw + rr8 + (((lane >> 3) & 1) ? 8 : 0);
    const int aCol = ((lane >> 4) & 1) ? 8 : 0;
    const int bRow = cw + rr8 + (((lane >> 4) & 1) ? 8 : 0);
    const int bCol = ((lane >> 3) & 1) ? 8 : 0;

    const uint32_t aHi = su32(&sAhi[aRow * AS + aCol]);
    const uint32_t aLo = su32(&sAlo[aRow * AS + aCol]);
    const uint32_t bHi0 = su32(&sWhi[bRow * AS + bCol]);
    const uint32_t bHi1 = su32(&sWhi[(bRow + 16) * AS + bCol]);
    const uint32_t bLo0 = su32(&sWlo[bRow * AS + bCol]);
    const uint32_t bLo1 = su32(&sWlo[(bRow + 16) * AS + bCol]);

    #pragma unroll
    for (int k16 = 0; k16 < KPER / 16; k16++) {
        const uint32_t ko = k16 * 32;
        uint32_t ah[4], al[4], bh[8], bl[8];
        ldsm4(ah, aHi + ko);
        ldsm4(al, aLo + ko);
        ldsm4(bh,     bHi0 + ko);
        ldsm4(bh + 4, bHi1 + ko);
        ldsm4(bl,     bLo0 + ko);
        ldsm4(bl + 4, bLo1 + ko);
        #pragma unroll
        for (int nb = 0; nb < 4; nb++) {
            mma_bf16(acc[nb], ah, bh[nb * 2], bh[nb * 2 + 1]);
            mma_bf16(acc[nb], ah, bl[nb * 2], bl[nb * 2 + 1]);
            mma_bf16(acc[nb], al, bh[nb * 2], bh[nb * 2 + 1]);
        }
    }
}

__device__ __forceinline__ void store_partial_mma(int slot, int tid, const float acc[4][4]) {
    float* p = &g_part[(size_t)slot * 4096];
    const int lane = tid & 31, w = tid >> 5;
    const int rw = (w >> 1) * 16, cw = (w & 1) * 32;
    const int grp = lane >> 2, tig = lane & 3;
    float* pr = p + (rw + grp) * 64 + cw + 2 * tig;
    #pragma unroll
    for (int nb = 0; nb < 4; nb++) {
        __stcg((float2*)(pr + nb * 8),          make_float2(acc[nb][0], acc[nb][1]));
        __stcg((float2*)(pr + 8 * 64 + nb * 8), make_float2(acc[nb][2], acc[nb][3]));
    }
}

// ---------- group reduce + activation (float4) ----------
template<int NSPLIT>
__device__ __forceinline__ void group_reduce(
    int tile, int s, int tid, const float* bias, const float* bias2,
    int mode, float* out, int ldo, const float* e1, const float* e2)
{
    const int per4 = 4096 / NSPLIT / 4;
    const float4* pt = (const float4*)&g_part[(size_t)(tile * NSPLIT) * 4096];
    for (int i4 = tid; i4 < per4; i4 += 256) {
        const int local4 = s * per4 + i4;
        float4 v = make_float4(0.f, 0.f, 0.f, 0.f);
        #pragma unroll
        for (int ss = 0; ss < NSPLIT; ss++) {
            float4 u = __ldcg(pt + (size_t)ss * 1024 + local4);
            v.x += u.x; v.y += u.y; v.z += u.z; v.w += u.w;
        }
        const int local = local4 * 4;
        const int m  = local >> 6;
        const int ng = tile * 64 + (local & 63);
        float4 b = __ldg((const float4*)&bias[ng]);
        v.x += b.x; v.y += b.y; v.z += b.z; v.w += b.w;
        if (bias2) {
            float4 b2 = __ldg((const float4*)&bias2[ng]);
            v.x += b2.x; v.y += b2.y; v.z += b2.z; v.w += b2.w;
        }
        float4 r;
        switch (mode) {
            case 0:
                r = make_float4(tanhf(v.x), tanhf(v.y), tanhf(v.z), tanhf(v.w));
                break;
            case 1:
                if (ng < Hd) r = make_float4(fmaxf(v.x,0.f), fmaxf(v.y,0.f), fmaxf(v.z,0.f), fmaxf(v.w,0.f));
                else         r = make_float4(1.f/(1.f+expf(-v.x)), 1.f/(1.f+expf(-v.y)),
                                             1.f/(1.f+expf(-v.z)), 1.f/(1.f+expf(-v.w)));
                break;
            case 2:
                if (ng < Hd) r = make_float4(tanhf(v.x), tanhf(v.y), tanhf(v.z), tanhf(v.w));
                else         r = make_float4(fmaxf(v.x,0.f), fmaxf(v.y,0.f), fmaxf(v.z,0.f), fmaxf(v.w,0.f));
                break;
            default: {
                float4 a1 = __ldcg((const float4*)&e1[(size_t)m * 2 * Hd + ng]);
                float4 a2 = __ldcg((const float4*)&e2[(size_t)m * 2 * Hd + ng]);
                r.x = g_c[2]*tanhf(v.x) + g_c[0]*a1.x + g_c[1]*a2.x;
                r.y = g_c[2]*tanhf(v.y) + g_c[0]*a1.y + g_c[1]*a2.y;
                r.z = g_c[2]*tanhf(v.z) + g_c[0]*a1.z + g_c[1]*a2.z;
                r.w = g_c[2]*tanhf(v.w) + g_c[0]*a1.w + g_c[1]*a2.w;
            }
        }
        __stcg((float4*)&out[(size_t)m * ldo + ng], r);
    }
}

// ---------- fp32 FFMA2 gemm (final GEMM only) ----------
template<int KPER>
__device__ __forceinline__ void gemm64_f32(
    const float* A, int lda, const float* Wp, int n0, int Nlim,
    float (*As)[TM][ASf], float (*Wsm)[TN][WSf], int tid, float vals[4][4])
{
    const int mr0 = tid >> 3, mr1 = mr0 + 32;
    const int kf  = (tid & 7) * 4;
    const float* arow0 = A + (size_t)mr0 * lda + kf;
    const float* arow1 = A + (size_t)mr1 * lda + kf;
    const bool wok0 = (n0 + mr0) < Nlim;
    const bool wok1 = (n0 + mr1) < Nlim;
    const float* wrow0 = Wp + (size_t)(n0 + mr0) * Hd + kf;
    const float* wrow1 = Wp + (size_t)(n0 + mr1) * Hd + kf;

    const int r  = tid >> 4;
    const int c  = tid & 15;
    const int mt = r * 4;

    unsigned long long acc[4][4];
    #pragma unroll
    for (int i = 0; i < 4; i++)
        #pragma unroll
        for (int j = 0; j < 4; j++) acc[i][j] = 0ull;

    const int nch = KPER / KCH;
    const float4 z4 = make_float4(0.f, 0.f, 0.f, 0.f);

    float4 va0 = __ldcg((const float4*)(arow0));
    float4 va1 = __ldcg((const float4*)(arow1));
    float4 vw0 = wok0 ? __ldg((const float4*)(wrow0)) : z4;
    float4 vw1 = wok1 ? __ldg((const float4*)(wrow1)) : z4;
    *(float4*)&As[0][mr0][kf] = va0;
    *(float4*)&As[0][mr1][kf] = va1;
    *(float2*)&Wsm[0][mr0][kf]     = make_float2(vw0.x, vw0.y);
    *(float2*)&Wsm[0][mr0][kf + 2] = make_float2(vw0.z, vw0.w);
    *(float2*)&Wsm[0][mr1][kf]     = make_float2(vw1.x, vw1.y);
    *(float2*)&Wsm[0][mr1][kf + 2] = make_float2(vw1.z, vw1.w);
    __syncthreads();

    for (int ch = 0; ch < nch; ch++) {
        const int b = ch & 1;
        const bool more = (ch + 1) < nch;
        if (more) {
            const int o = (ch + 1) * KCH;
            va0 = __ldcg((const float4*)(arow0 + o));
            va1 = __ldcg((const float4*)(arow1 + o));
            vw0 = wok0 ? __ldg((const float4*)(wrow0 + o)) : z4;
            vw1 = wok1 ? __ldg((const float4*)(wrow1 + o)) : z4;
        }
        #pragma unroll
        for (int k4 = 0; k4 < KCH / 4; k4++) {
            ulonglong2 a[4];
            #pragma unroll
            for (int i = 0; i < 4; i++)
                a[i] = *(const ulonglong2*)&As[b][mt + i][k4 * 4];
            #pragma unroll
            for (int j = 0; j < 4; j++) {
                const int n = c + 16 * j;
                unsigned long long wlo = *(const unsigned long long*)&Wsm[b][n][k4 * 4];
                unsigned long long whi = *(const unsigned long long*)&Wsm[b][n][k4 * 4 + 2];
                #pragma unroll
                for (int i = 0; i < 4; i++) {
                    acc[i][j] = ffma2(a[i].x, wlo, acc[i][j]);
                    acc[i][j] = ffma2(a[i].y, whi, acc[i][j]);
                }
            }
        }
        if (more) {
            const int nb = (ch + 1) & 1;
            *(float4*)&As[nb][mr0][kf] = va0;
            *(float4*)&As[nb][mr1][kf] = va1;
            *(float2*)&Wsm[nb][mr0][kf]     = make_float2(vw0.x, vw0.y);
            *(float2*)&Wsm[nb][mr0][kf + 2] = make_float2(vw0.z, vw0.w);
            *(float2*)&Wsm[nb][mr1][kf]     = make_float2(vw1.x, vw1.y);
            *(float2*)&Wsm[nb][mr1][kf + 2] = make_float2(vw1.z, vw1.w);
        }
        __syncthreads();
    }

    #pragma unroll
    for (int i = 0; i < 4; i++)
        #pragma unroll
        for (int j = 0; j < 4; j++) vals[i][j] = unpack_sum(acc[i][j]);
}

// ---------- persistent kernel ----------
__global__ void __launch_bounds__(256, 2) rnn_persistent(PArgs p) {
    extern __shared__ __align__(16) char smem[];

    const int bid = blockIdx.x;
    const int tid = threadIdx.x;

    if (bid == 0 && tid == 0) {
        const int rows[3] = {1, 3, 5};
        float wgt[3];
        for (int i = 0; i < 3; i++) {
            float acc = p.b_sum[rows[i]];
            for (int j = 0; j < 12; j++) acc += p.W_sum[rows[i] * 12 + j] * p.actions[j];
            wgt[i] = acc;
        }
        float mx = fmaxf(wgt[0], fmaxf(wgt[1], wgt[2]));
        float e0 = expf(wgt[0] - mx), e1 = expf(wgt[1] - mx), e2 = expf(wgt[2] - mx);
        float s = e0 + e1 + e2;
        g_c[0] = e0 / s; g_c[1] = e1 / s; g_c[2] = e2 / s;
    }

    unsigned bar = 0;

    // Pre-split recurrent weights (Ws then W0) into bf16 hi/lo, once per launch.
    {
        const int gtid = bid * 256 + tid;
        const int total4 = 7 * 1024 * 1024 / 4;
        const int ws4    = 6 * 1024 * 1024 / 4;
        for (int i = gtid; i < total4; i += GRID * 256) {
            float4 v = (i < ws4) ? __ldg((const float4*)p.Ws + i)
                                 : __ldg((const float4*)p.W0 + (i - ws4));
            split4(&g_Whi[(size_t)i * 4], &g_Wlo[(size_t)i * 4], v);
        }
    }
    grid_barrier(++bar);

    float* gh0 = g_h[0];
    float* gh1 = g_h[1];
    const int tile16 = bid >> 4, s16 = bid & 15;
    const int tile8  = bid >> 3, s8  = bid & 7;

    // Static per-CTA weight tile pointers for the 4 phases
    const size_t wo1 = (s16 < 8)
        ? (size_t)(tile16 * 64) * Hd + s16 * 128
        : (size_t)(6 * 1024 + tile16 * 64) * Hd + (s16 - 8) * 128;
    const size_t wo2 = (size_t)(1024 + tile8 * 64) * Hd + s8 * 128;
    const size_t wo3 = (size_t)(3 * 1024 + tile8 * 64) * Hd + s8 * 128;
    const size_t wo4 = (size_t)(5 * 1024 + tile16 * 64) * Hd + s16 * 64;

    // Prime phase-1 W (async; waited before first compute)
    stage_W_async<128>(g_Whi + wo1, g_Wlo + wo1, smem, tid);

    for (int t = 0; t < NSTEP; t++) {
        const float* hin  = (t == 0) ? p.h : ((t & 1) ? gh1 : gh0);
        float*       hout = ((t + 1) & 1) ? gh1 : gh0;

        // ---- phase 1: out1 = tanh(h @ Ws0^T + wv[idx] @ W0^T + bs0 + b0)  (nsplit=16) ----
        {
            float acc[4][4] = {};
            if (s16 < 8)
                stage_A<128, false>(hin, Hd, s16 * 128, nullptr, nullptr, smem, tid);
            else
                stage_A<128, true>(nullptr, 0, (s16 - 8) * 128, p.wv, p.bi + (t + 1), smem, tid);
            cp_wait0();
            __syncthreads();
            compute_mma<128>(smem, tid, acc);
            store_partial_mma(bid, tid, acc);
            __syncthreads();                       // all warps done reading sW
            stage_W_async<128>(g_Whi + wo2, g_Wlo + wo2, smem, tid);
        }
        group_sync(&g_tile_ctr[tile16], (unsigned)(t + 1) * 16u);
        group_reduce<16>(tile16, s16, tid, p.bs, p.b0, 0, g_out1, Hd, nullptr, nullptr);
        grid_barrier(++bar);

        // ---- phase 2: [out2|out3] = [relu|sigmoid](out1 @ [Ws1;Ws2]^T + b)  (nsplit=8) ----
        {
            float acc[4][4] = {};
            stage_A<128, false>(g_out1, Hd, s8 * 128, nullptr, nullptr, smem, tid);
            cp_wait0();
            __syncthreads();
            compute_mma<128>(smem, tid, acc);
            store_partial_mma(bid, tid, acc);
            __syncthreads();
            stage_W_async<128>(g_Whi + wo3, g_Wlo + wo3, smem, tid);
        }
        group_sync(&g_tile_ctr[16 + tile8], (unsigned)(t + 1) * 8u);
        group_reduce<8>(tile8, s8, tid, p.bs + Hd, nullptr, 1, g_out23, 2 * Hd, nullptr, nullptr);
        grid_barrier(++bar);

        // ---- phase 3: [out4|out5] = [tanh|relu](out3 @ [Ws3;Ws4]^T + b)  (nsplit=8) ----
        {
            float acc[4][4] = {};
            stage_A<128, false>(g_out23 + Hd, 2 * Hd, s8 * 128, nullptr, nullptr, smem, tid);
            cp_wait0();
            __syncthreads();
            compute_mma<128>(smem, tid, acc);
            store_partial_mma(bid, tid, acc);
            __syncthreads();
            stage_W_async<64>(g_Whi + wo4, g_Wlo + wo4, smem, tid);
        }
        group_sync(&g_tile_ctr[48 + tile8], (unsigned)(t + 1) * 8u);
        group_reduce<8>(tile8, s8, tid, p.bs + 3 * Hd, nullptr, 2, g_out45, 2 * Hd, nullptr, nullptr);
        grid_barrier(++bar);

        // ---- phase 4: h_new = c2*tanh(out5 @ Ws5^T + bs5) + c0*out2 + c1*out4  (nsplit=16) ----
        {
            float acc[4][4] = {};
            stage_A<64, false>(g_out45 + Hd, 2 * Hd, s16 * 64, nullptr, nullptr, smem, tid);
            cp_wait0();
            __syncthreads();
            compute_mma<64>(smem, tid, acc);
            store_partial_mma(bid, tid, acc);
            __syncthreads();
            stage_W_async<128>(g_Whi + wo1, g_Wlo + wo1, smem, tid);   // next t's phase 1
        }
        group_sync(&g_tile_ctr[80 + tile16], (unsigned)(t + 1) * 16u);
        group_reduce<16>(tile16, s16, tid, p.bs + 5 * Hd, nullptr, 3, hout, Hd, g_out23, g_out45);
        grid_barrier(++bar);
    }

    // drain the dangling phase-1 prefetch before reusing smem for the final GEMM
    cp_wait0();
    __syncthreads();

    // ---- final: logits = h_final @ W_out^T + b_out  [64, 50000]  (fp32, DRAM-bound) ----
    {
        float (*As)[TM][ASf]  = (float (*)[TM][ASf])smem;
        float (*Wsm)[TN][WSf] = (float (*)[TN][WSf])(smem + 2 * TM * ASf * 4);
        const float* hf = gh1;   // (126+1)&1 == 1
        const int ntiles = (Cc + TN - 1) / TN;
        const int mt = (tid >> 4) * 4;
        const int c  = tid & 15;
        float vals[4][4];
        for (int tile = bid; tile < ntiles; tile += GRID) {
            gemm64_f32<Hd>(hf, Hd, p.W_out, tile * 64, Cc, As, Wsm, tid, vals);
            #pragma unroll
            for (int i = 0; i < 4; i++)
                #pragma unroll
                for (int j = 0; j < 4; j++) {
                    const int ng = tile * 64 + c + 16 * j;
                    if (ng < Cc)
                        p.out[(size_t)(mt + i) * Cc + ng] = vals[i][j] + __ldg(&p.b_out[ng]);
                }
        }
    }

    // exit handshake: last CTA resets all sync state for the next graph replay
    __threadfence();
    __syncthreads();
    if (tid == 0) {
        unsigned prev = atomicAdd(&g_exit_cnt, 1u);
        if (prev == GRID - 1u) {
            for (int i = 0; i < 96; i++) g_tile_ctr[i] = 0u;
            for (int i = 0; i < NLEAF; i++) g_leaf_cnt[i * LSTR] = 0u;
            g_root_cnt = 0u;
            g_root_gen = 0u;
            g_exit_cnt = 0u;
            __threadfence();
        }
    }
}

extern "C" void kernel_launch(void* const* d_in, const int* in_sizes, int n_in,
                              void* d_out, int out_size) {
    (void)in_sizes; (void)n_in; (void)out_size;
    PArgs p;
    p.wv      = (const float*)d_in[0];
    p.h       = (const float*)d_in[1];
    p.bi      = (const int*)  d_in[2];
    p.W0      = (const float*)d_in[3];
    p.b0      = (const float*)d_in[4];
    p.Ws      = (const float*)d_in[5];
    p.bs      = (const float*)d_in[6];
    p.W_out   = (const float*)d_in[7];
    p.b_out   = (const float*)d_in[8];
    p.W_sum   = (const float*)d_in[9];
    p.b_sum   = (const float*)d_in[10];
    p.actions = (const float*)d_in[11];
    p.out     = (float*)d_out;

    cudaFuncSetAttribute(rnn_persistent, cudaFuncAttributeMaxDynamicSharedMemorySize, SMEMB);
    cudaFuncSetAttribute(rnn_persistent, cudaFuncAttributePreferredSharedMemoryCarveout, 100);
    rnn_persistent<<<GRID, 256, SMEMB>>>(p);
}

// round 17
// speedup vs baseline: 1.0606x; 1.0606x over previous
#include <cuda_runtime.h>
#include <cuda_bf16.h>
#include <math.h>
#include <stdint.h>

#define Bq 64
#define Hd 1024
#define Tt 128
#define NSTEP 127
#define Cc 50000
#define GRID 128
#define TM 64
#define TN 64
#define KCH 32
#define ASf 36     // fp32 final-gemm A smem stride
#define WSf 34     // fp32 final-gemm W smem stride
#define AS 136     // bf16 smem row stride
#define REG64 (64 * AS)
#define BUFB (4 * 64 * AS * 2)     // 69,632 B per buffer
#define SMEMB (2 * BUFB)           // 139,264 B -> 1 CTA/SM

// Scratch (no cudaMalloc allowed)
__device__ float g_h[2][Bq * Hd];
__device__ float g_out1[Bq * Hd];
__device__ float g_out23[Bq * 2 * Hd];
__device__ float g_out45[Bq * 2 * Hd];
__device__ float g_part[128 * 4096];
__device__ float g_c[3];
__device__ unsigned g_tile_ctr[96];   // P1:0-15, P2:16-47, P3:48-79, P4:80-95
__device__ unsigned g_bar_cnt;
__device__ volatile unsigned g_bar_gen;
__device__ unsigned g_exit_cnt;
// Pre-split weights: rows 0-6143 = Ws[0..5], rows 6144-7167 = W0. [row][1024] bf16.
__device__ __nv_bfloat16 g_Whi[7 * 1024 * 1024];
__device__ __nv_bfloat16 g_Wlo[7 * 1024 * 1024];

struct PArgs {
    const float* wv; const float* h; const int* bi;
    const float* W0; const float* b0;
    const float* Ws; const float* bs;
    const float* W_out; const float* b_out;
    const float* W_sum; const float* b_sum; const float* actions;
    float* out;
};

// ---------- helpers ----------
__device__ __forceinline__ unsigned long long ffma2(unsigned long long a,
                                                    unsigned long long b,
                                                    unsigned long long c) {
    unsigned long long d;
    asm("fma.rn.f32x2 %0, %1, %2, %3;" : "=l"(d) : "l"(a), "l"(b), "l"(c));
    return d;
}
__device__ __forceinline__ float unpack_sum(unsigned long long p) {
    float lo, hi;
    asm("mov.b64 {%0, %1}, %2;" : "=f"(lo), "=f"(hi) : "l"(p));
    return lo + hi;
}
__device__ __forceinline__ uint32_t su32(const void* p) {
    return (uint32_t)__cvta_generic_to_shared(p);
}
__device__ __forceinline__ void cp16(uint32_t saddr, const void* g) {
    asm volatile("cp.async.cg.shared.global [%0], [%1], 16;" :: "r"(saddr), "l"(g));
}
__device__ __forceinline__ void cp_commit() { asm volatile("cp.async.commit_group;"); }
template<int N>
__device__ __forceinline__ void cp_wait() {
    asm volatile("cp.async.wait_group %0;" :: "n"(N));
}
__device__ __forceinline__ void ldsm4(uint32_t* r, uint32_t addr) {
    asm volatile("ldmatrix.sync.aligned.m8n8.x4.shared.b16 {%0,%1,%2,%3}, [%4];"
                 : "=r"(r[0]), "=r"(r[1]), "=r"(r[2]), "=r"(r[3]) : "r"(addr));
}
__device__ __forceinline__ void mma_bf16(float* d, const uint32_t* a, uint32_t b0, uint32_t b1) {
    asm volatile("mma.sync.aligned.m16n8k16.row.col.f32.bf16.bf16.f32 "
                 "{%0,%1,%2,%3}, {%4,%5,%6,%7}, {%8,%9}, {%0,%1,%2,%3};"
                 : "+f"(d[0]), "+f"(d[1]), "+f"(d[2]), "+f"(d[3])
                 : "r"(a[0]), "r"(a[1]), "r"(a[2]), "r"(a[3]), "r"(b0), "r"(b1));
}
__device__ __forceinline__ void split4(__nv_bfloat16* hi, __nv_bfloat16* lo, float4 v) {
    __nv_bfloat16 h0 = __float2bfloat16_rn(v.x), h1 = __float2bfloat16_rn(v.y);
    __nv_bfloat16 h2 = __float2bfloat16_rn(v.z), h3 = __float2bfloat16_rn(v.w);
    __nv_bfloat16 l0 = __float2bfloat16_rn(v.x - __bfloat162float(h0));
    __nv_bfloat16 l1 = __float2bfloat16_rn(v.y - __bfloat162float(h1));
    __nv_bfloat16 l2 = __float2bfloat16_rn(v.z - __bfloat162float(h2));
    __nv_bfloat16 l3 = __float2bfloat16_rn(v.w - __bfloat162float(h3));
    __nv_bfloat162 a; a.x = h0; a.y = h1; *(__nv_bfloat162*)(hi)     = a;
    __nv_bfloat162 b; b.x = h2; b.y = h3; *(__nv_bfloat162*)(hi + 2) = b;
    __nv_bfloat162 c; c.x = l0; c.y = l1; *(__nv_bfloat162*)(lo)     = c;
    __nv_bfloat162 d; d.x = l2; d.y = l3; *(__nv_bfloat162*)(lo + 2) = d;
}

// ---------- sync (flat, proven) ----------
// Safe: GRID=128 <= 148 SMs, 1 CTA/SM (139KB smem) => all CTAs resident wave 1.
__device__ __forceinline__ void grid_barrier(unsigned target) {
    __syncthreads();
    if (threadIdx.x == 0) {
        __threadfence();
        unsigned prev = atomicAdd(&g_bar_cnt, 1u);
        if (prev == GRID - 1u) {
            g_bar_cnt = 0u;
            __threadfence();
            g_bar_gen = target;
        } else {
            while (g_bar_gen < target) { }
        }
        __threadfence();
    }
    __syncthreads();
}
__device__ __forceinline__ void group_sync(unsigned* ctr, unsigned target) {
    __syncthreads();
    if (threadIdx.x == 0) {
        __threadfence();
        atomicAdd(ctr, 1u);
        while (*(volatile unsigned*)ctr < target) { }
        __threadfence();
    }
    __syncthreads();
}

// ---------- staging ----------
template<bool GATHER>
__device__ __forceinline__ void ldA_chunk(float4 r[8], const float* A, int lda,
                                          const float* wv, const int* idx, int kk, int tid) {
    const int r0 = tid >> 3;
    const int kf = (tid & 7) * 4;
    #pragma unroll
    for (int rr = 0; rr < 2; rr++) {
        const int row = r0 + rr * 32;
        const float* ar;
        if (GATHER) ar = wv + (size_t)__ldg(idx + row * Tt) * Hd;
        else        ar = A + (size_t)row * lda;
        #pragma unroll
        for (int c = 0; c < 4; c++)
            r[rr * 4 + c] = GATHER ? __ldg((const float4*)(ar + kk + kf + 32 * c))
                                   : __ldcg((const float4*)(ar + kk + kf + 32 * c));
    }
}
__device__ __forceinline__ void stsA(char* buf, const float4 r[8], int tid) {
    __nv_bfloat16* hi = (__nv_bfloat16*)buf;
    __nv_bfloat16* lo = hi + REG64;
    const int r0 = tid >> 3;
    const int kf = (tid & 7) * 4;
    #pragma unroll
    for (int rr = 0; rr < 2; rr++) {
        const int row = r0 + rr * 32;
        #pragma unroll
        for (int c = 0; c < 4; c++)
            split4(&hi[row * AS + kf + 32 * c], &lo[row * AS + kf + 32 * c], r[rr * 4 + c]);
    }
}
// W chunk from pre-split bf16 via cp.async (one commit group per call)
__device__ __forceinline__ void cpW(char* buf, const __nv_bfloat16* Whi,
                                    const __nv_bfloat16* Wlo, int kk, int tid) {
    __nv_bfloat16* hi = (__nv_bfloat16*)buf + 2 * REG64;
    __nv_bfloat16* lo = (__nv_bfloat16*)buf + 3 * REG64;
    const int r0 = tid >> 3;
    const int k  = (tid & 7) * 16;
    #pragma unroll
    for (int rr = 0; rr < 2; rr++) {
        const int row = r0 + rr * 32;
        cp16(su32(&hi[row * AS + k]),     Whi + (size_t)row * Hd + kk + k);
        cp16(su32(&hi[row * AS + k + 8]), Whi + (size_t)row * Hd + kk + k + 8);
        cp16(su32(&lo[row * AS + k]),     Wlo + (size_t)row * Hd + kk + k);
        cp16(su32(&lo[row * AS + k + 8]), Wlo + (size_t)row * Hd + kk + k + 8);
    }
    cp_commit();
}

// ---------- compute one staged 128-K chunk (bf16x3) ----------
__device__ __forceinline__ void compute_mma(char* buf, int tid, float acc[4][4]) {
    __nv_bfloat16* sAhi = (__nv_bfloat16*)buf;
    __nv_bfloat16* sAlo = sAhi + REG64;
    __nv_bfloat16* sWhi = sAhi + 2 * REG64;
    __nv_bfloat16* sWlo = sAhi + 3 * REG64;

    const int lane = tid & 31;
    const int w    = tid >> 5;
    const int rw = (w >> 1) * 16;
    const int cw = (w & 1) * 32;
    const int rr8 = lane & 7;
    const int aRow = rw + rr8 + (((lane >> 3) & 1) ? 8 : 0);
    const int aCol = ((lane >> 4) & 1) ? 8 : 0;
    const int bRow = cw + rr8 + (((lane >> 4) & 1) ? 8 : 0);
    const int bCol = ((lane >> 3) & 1) ? 8 : 0;

    const uint32_t aHi = su32(&sAhi[aRow * AS + aCol]);
    const uint32_t aLo = su32(&sAlo[aRow * AS + aCol]);
    const uint32_t bHi0 = su32(&sWhi[bRow * AS + bCol]);
    const uint32_t bHi1 = su32(&sWhi[(bRow + 16) * AS + bCol]);
    const uint32_t bLo0 = su32(&sWlo[bRow * AS + bCol]);
    const uint32_t bLo1 = su32(&sWlo[(bRow + 16) * AS + bCol]);

    #pragma unroll
    for (int k16 = 0; k16 < 8; k16++) {
        const uint32_t ko = k16 * 32;
        uint32_t ah[4], al[4], bh[8], bl[8];
        ldsm4(ah, aHi + ko);
        ldsm4(al, aLo + ko);
        ldsm4(bh,     bHi0 + ko);
        ldsm4(bh + 4, bHi1 + ko);
        ldsm4(bl,     bLo0 + ko);
        ldsm4(bl + 4, bLo1 + ko);
        #pragma unroll
        for (int nb = 0; nb < 4; nb++) {
            mma_bf16(acc[nb], ah, bh[nb * 2], bh[nb * 2 + 1]);
            mma_bf16(acc[nb], ah, bl[nb * 2], bl[nb * 2 + 1]);
            mma_bf16(acc[nb], al, bh[nb * 2], bh[nb * 2 + 1]);
        }
    }
}

// K=256 phase: double-buffered 2x128 chunks. Caller pre-issued cpW(b0, W, kk=0).
template<bool GATHER>
__device__ __forceinline__ void phase_K256(
    const float* A, int lda, int kbase,
    const float* wv, const int* idx,
    const __nv_bfloat16* Whi, const __nv_bfloat16* Wlo,
    char* b0, char* b1, int tid, float acc[4][4])
{
    float4 ra[8];
    ldA_chunk<GATHER>(ra, A, lda, wv, idx, kbase, tid);
    stsA(b0, ra, tid);
    cpW(b1, Whi, Wlo, 128, tid);                    // chunk1 W (pending behind chunk0's)
    ldA_chunk<GATHER>(ra, A, lda, wv, idx, kbase + 128, tid);
    cp_wait<1>();                                   // chunk0 W done (chunk1 may pend)
    __syncthreads();
    compute_mma(b0, tid, acc);
    stsA(b1, ra, tid);
    cp_wait<0>();                                   // chunk1 W done
    __syncthreads();
    compute_mma(b1, tid, acc);
}

// K=128 phase (P4). Caller pre-issued cpW(b0, W, 0).
__device__ __forceinline__ void phase_K128(
    const float* A, int lda, int kbase, char* b0, int tid, float acc[4][4])
{
    float4 ra[8];
    ldA_chunk<false>(ra, A, lda, nullptr, nullptr, kbase, tid);
    stsA(b0, ra, tid);
    cp_wait<0>();
    __syncthreads();
    compute_mma(b0, tid, acc);
}

__device__ __forceinline__ void store_partial_mma(int slot, int tid, const float acc[4][4]) {
    float* p = &g_part[(size_t)slot * 4096];
    const int lane = tid & 31, w = tid >> 5;
    const int rw = (w >> 1) * 16, cw = (w & 1) * 32;
    const int grp = lane >> 2, tig = lane & 3;
    float* pr = p + (rw + grp) * 64 + cw + 2 * tig;
    #pragma unroll
    for (int nb = 0; nb < 4; nb++) {
        __stcg((float2*)(pr + nb * 8),          make_float2(acc[nb][0], acc[nb][1]));
        __stcg((float2*)(pr + 8 * 64 + nb * 8), make_float2(acc[nb][2], acc[nb][3]));
    }
}

// ---------- group reduce + activation (float4) ----------
template<int NSPLIT>
__device__ __forceinline__ void group_reduce(
    int tile, int s, int tid, const float* bias, const float* bias2,
    int mode, float* out, int ldo, const float* e1, const float* e2)
{
    const int per4 = 4096 / NSPLIT / 4;    // 128 (nsplit8) or 256 (nsplit4)
    const float4* pt = (const float4*)&g_part[(size_t)(tile * NSPLIT) * 4096];
    for (int i4 = tid; i4 < per4; i4 += 256) {
        const int local4 = s * per4 + i4;
        float4 v = make_float4(0.f, 0.f, 0.f, 0.f);
        #pragma unroll
        for (int ss = 0; ss < NSPLIT; ss++) {
            float4 u = __ldcg(pt + (size_t)ss * 1024 + local4);
            v.x += u.x; v.y += u.y; v.z += u.z; v.w += u.w;
        }
        const int local = local4 * 4;
        const int m  = local >> 6;
        const int ng = tile * 64 + (local & 63);
        float4 b = __ldg((const float4*)&bias[ng]);
        v.x += b.x; v.y += b.y; v.z += b.z; v.w += b.w;
        if (bias2) {
            float4 b2 = __ldg((const float4*)&bias2[ng]);
            v.x += b2.x; v.y += b2.y; v.z += b2.z; v.w += b2.w;
        }
        float4 r;
        switch (mode) {
            case 0:
                r = make_float4(tanhf(v.x), tanhf(v.y), tanhf(v.z), tanhf(v.w));
                break;
            case 1:
                if (ng < Hd) r = make_float4(fmaxf(v.x,0.f), fmaxf(v.y,0.f), fmaxf(v.z,0.f), fmaxf(v.w,0.f));
                else         r = make_float4(1.f/(1.f+expf(-v.x)), 1.f/(1.f+expf(-v.y)),
                                             1.f/(1.f+expf(-v.z)), 1.f/(1.f+expf(-v.w)));
                break;
            case 2:
                if (ng < Hd) r = make_float4(tanhf(v.x), tanhf(v.y), tanhf(v.z), tanhf(v.w));
                else         r = make_float4(fmaxf(v.x,0.f), fmaxf(v.y,0.f), fmaxf(v.z,0.f), fmaxf(v.w,0.f));
                break;
            default: {
                float4 a1 = __ldcg((const float4*)&e1[(size_t)m * 2 * Hd + ng]);
                float4 a2 = __ldcg((const float4*)&e2[(size_t)m * 2 * Hd + ng]);
                r.x = g_c[2]*tanhf(v.x) + g_c[0]*a1.x + g_c[1]*a2.x;
                r.y = g_c[2]*tanhf(v.y) + g_c[0]*a1.y + g_c[1]*a2.y;
                r.z = g_c[2]*tanhf(v.z) + g_c[0]*a1.z + g_c[1]*a2.z;
                r.w = g_c[2]*tanhf(v.w) + g_c[0]*a1.w + g_c[1]*a2.w;
            }
        }
        __stcg((float4*)&out[(size_t)m * ldo + ng], r);
    }
}

// ---------- fp32 FFMA2 gemm (final GEMM only) ----------
template<int KPER>
__device__ __forceinline__ void gemm64_f32(
    const float* A, int lda, const float* Wp, int n0, int Nlim,
    float (*As)[TM][ASf], float (*Wsm)[TN][WSf], int tid, float vals[4][4])
{
    const int mr0 = tid >> 3, mr1 = mr0 + 32;
    const int kf  = (tid & 7) * 4;
    const float* arow0 = A + (size_t)mr0 * lda + kf;
    const float* arow1 = A + (size_t)mr1 * lda + kf;
    const bool wok0 = (n0 + mr0) < Nlim;
    const bool wok1 = (n0 + mr1) < Nlim;
    const float* wrow0 = Wp + (size_t)(n0 + mr0) * Hd + kf;
    const float* wrow1 = Wp + (size_t)(n0 + mr1) * Hd + kf;

    const int r  = tid >> 4;
    const int c  = tid & 15;
    const int mt = r * 4;

    unsigned long long acc[4][4];
    #pragma unroll
    for (int i = 0; i < 4; i++)
        #pragma unroll
        for (int j = 0; j < 4; j++) acc[i][j] = 0ull;

    const int nch = KPER / KCH;
    const float4 z4 = make_float4(0.f, 0.f, 0.f, 0.f);

    float4 va0 = __ldcg((const float4*)(arow0));
    float4 va1 = __ldcg((const float4*)(arow1));
    float4 vw0 = wok0 ? __ldg((const float4*)(wrow0)) : z4;
    float4 vw1 = wok1 ? __ldg((const float4*)(wrow1)) : z4;
    *(float4*)&As[0][mr0][kf] = va0;
    *(float4*)&As[0][mr1][kf] = va1;
    *(float2*)&Wsm[0][mr0][kf]     = make_float2(vw0.x, vw0.y);
    *(float2*)&Wsm[0][mr0][kf + 2] = make_float2(vw0.z, vw0.w);
    *(float2*)&Wsm[0][mr1][kf]     = make_float2(vw1.x, vw1.y);
    *(float2*)&Wsm[0][mr1][kf + 2] = make_float2(vw1.z, vw1.w);
    __syncthreads();

    for (int ch = 0; ch < nch; ch++) {
        const int b = ch & 1;
        const bool more = (ch + 1) < nch;
        if (more) {
            const int o = (ch + 1) * KCH;
            va0 = __ldcg((const float4*)(arow0 + o));
            va1 = __ldcg((const float4*)(arow1 + o));
            vw0 = wok0 ? __ldg((const float4*)(wrow0 + o)) : z4;
            vw1 = wok1 ? __ldg((const float4*)(wrow1 + o)) : z4;
        }
        #pragma unroll
        for (int k4 = 0; k4 < KCH / 4; k4++) {
            ulonglong2 a[4];
            #pragma unroll
            for (int i = 0; i < 4; i++)
                a[i] = *(const ulonglong2*)&As[b][mt + i][k4 * 4];
            #pragma unroll
            for (int j = 0; j < 4; j++) {
                const int n = c + 16 * j;
                unsigned long long wlo = *(const unsigned long long*)&Wsm[b][n][k4 * 4];
                unsigned long long whi = *(const unsigned long long*)&Wsm[b][n][k4 * 4 + 2];
                #pragma unroll
                for (int i = 0; i < 4; i++) {
                    acc[i][j] = ffma2(a[i].x, wlo, acc[i][j]);
                    acc[i][j] = ffma2(a[i].y, whi, acc[i][j]);
                }
            }
        }
        if (more) {
            const int nb = (ch + 1) & 1;
            *(float4*)&As[nb][mr0][kf] = va0;
            *(float4*)&As[nb][mr1][kf] = va1;
            *(float2*)&Wsm[nb][mr0][kf]     = make_float2(vw0.x, vw0.y);
            *(float2*)&Wsm[nb][mr0][kf + 2] = make_float2(vw0.z, vw0.w);
            *(float2*)&Wsm[nb][mr1][kf]     = make_float2(vw1.x, vw1.y);
            *(float2*)&Wsm[nb][mr1][kf + 2] = make_float2(vw1.z, vw1.w);
        }
        __syncthreads();
    }

    #pragma unroll
    for (int i = 0; i < 4; i++)
        #pragma unroll
        for (int j = 0; j < 4; j++) vals[i][j] = unpack_sum(acc[i][j]);
}

// ---------- persistent kernel ----------
__global__ void __launch_bounds__(256) rnn_persistent(PArgs p) {
    extern __shared__ __align__(16) char smem[];
    char* b0 = smem;
    char* b1 = smem + BUFB;

    const int bid = blockIdx.x;
    const int tid = threadIdx.x;

    if (bid == 0 && tid == 0) {
        const int rows[3] = {1, 3, 5};
        float wgt[3];
        for (int i = 0; i < 3; i++) {
            float acc = p.b_sum[rows[i]];
            for (int j = 0; j < 12; j++) acc += p.W_sum[rows[i] * 12 + j] * p.actions[j];
            wgt[i] = acc;
        }
        float mx = fmaxf(wgt[0], fmaxf(wgt[1], wgt[2]));
        float e0 = expf(wgt[0] - mx), e1 = expf(wgt[1] - mx), e2 = expf(wgt[2] - mx);
        float s = e0 + e1 + e2;
        g_c[0] = e0 / s; g_c[1] = e1 / s; g_c[2] = e2 / s;
    }

    unsigned bar = 0;

    // Pre-split recurrent weights (Ws then W0) into bf16 hi/lo, once per launch.
    {
        const int gtid = bid * 256 + tid;
        const int total4 = 7 * 1024 * 1024 / 4;
        const int ws4    = 6 * 1024 * 1024 / 4;
        for (int i = gtid; i < total4; i += GRID * 256) {
            float4 v = (i < ws4) ? __ldg((const float4*)p.Ws + i)
                                 : __ldg((const float4*)p.W0 + (i - ws4));
            split4(&g_Whi[(size_t)i * 4], &g_Wlo[(size_t)i * 4], v);
        }
    }
    grid_barrier(++bar);

    float* gh0 = g_h[0];
    float* gh1 = g_h[1];
    const int t16 = bid >> 3, s8 = bid & 7;   // P1/P4: 16 tiles x 8 splits
    const int t32 = bid >> 2, s4 = bid & 3;   // P2/P3: 32 tiles x 4 splits

    // Per-CTA weight tile base pointers
    const size_t wo1 = (s8 < 4)
        ? (size_t)(t16 * 64) * Hd + s8 * 256
        : (size_t)(6 * 1024 + t16 * 64) * Hd + (s8 - 4) * 256;
    const size_t wo2 = (size_t)(1024 + t32 * 64) * Hd + s4 * 256;
    const size_t wo3 = (size_t)(3 * 1024 + t32 * 64) * Hd + s4 * 256;
    const size_t wo4 = (size_t)(5 * 1024 + t16 * 64) * Hd + s8 * 128;

    // Prime P1 chunk0 W into b0
    cpW(b0, g_Whi + wo1, g_Wlo + wo1, 0, tid);

    for (int t = 0; t < NSTEP; t++) {
        const float* hin  = (t == 0) ? p.h : ((t & 1) ? gh1 : gh0);
        float*       hout = ((t + 1) & 1) ? gh1 : gh0;

        // ---- P1: out1 = tanh(h@Ws0^T + wv[idx]@W0^T + bs0 + b0)  (K=256/CTA, nsplit=8) ----
        {
            float acc[4][4] = {};
            if (s8 < 4)
                phase_K256<false>(hin, Hd, s8 * 256, nullptr, nullptr,
                                  g_Whi + wo1, g_Wlo + wo1, b0, b1, tid, acc);
            else
                phase_K256<true>(nullptr, 0, (s8 - 4) * 256, p.wv, p.bi + (t + 1),
                                 g_Whi + wo1, g_Wlo + wo1, b0, b1, tid, acc);
            store_partial_mma(bid, tid, acc);
            __syncthreads();
            cpW(b0, g_Whi + wo2, g_Wlo + wo2, 0, tid);
        }
        group_sync(&g_tile_ctr[t16], (unsigned)(t + 1) * 8u);
        group_reduce<8>(t16, s8, tid, p.bs, p.b0, 0, g_out1, Hd, nullptr, nullptr);
        grid_barrier(++bar);

        // ---- P2: [out2|out3] = [relu|sigmoid](out1@[Ws1;Ws2]^T + b)  (K=256, nsplit=4) ----
        {
            float acc[4][4] = {};
            phase_K256<false>(g_out1, Hd, s4 * 256, nullptr, nullptr,
                              g_Whi + wo2, g_Wlo + wo2, b0, b1, tid, acc);
            store_partial_mma(bid, tid, acc);
            __syncthreads();
            cpW(b0, g_Whi + wo3, g_Wlo + wo3, 0, tid);
        }
        group_sync(&g_tile_ctr[16 + t32], (unsigned)(t + 1) * 4u);
        group_reduce<4>(t32, s4, tid, p.bs + Hd, nullptr, 1, g_out23, 2 * Hd, nullptr, nullptr);
        grid_barrier(++bar);

        // ---- P3: [out4|out5] = [tanh|relu](out3@[Ws3;Ws4]^T + b)  (K=256, nsplit=4) ----
        {
            float acc[4][4] = {};
            phase_K256<false>(g_out23 + Hd, 2 * Hd, s4 * 256, nullptr, nullptr,
                              g_Whi + wo3, g_Wlo + wo3, b0, b1, tid, acc);
            store_partial_mma(bid, tid, acc);
            __syncthreads();
            cpW(b0, g_Whi + wo4, g_Wlo + wo4, 0, tid);
        }
        group_sync(&g_tile_ctr[48 + t32], (unsigned)(t + 1) * 4u);
        group_reduce<4>(t32, s4, tid, p.bs + 3 * Hd, nullptr, 2, g_out45, 2 * Hd, nullptr, nullptr);
        grid_barrier(++bar);

        // ---- P4: h' = c2*tanh(out5@Ws5^T + bs5) + c0*out2 + c1*out4  (K=128, nsplit=8) ----
        {
            float acc[4][4] = {};
            phase_K128(g_out45 + Hd, 2 * Hd, s8 * 128, b0, tid, acc);
            store_partial_mma(bid, tid, acc);
            __syncthreads();
            cpW(b0, g_Whi + wo1, g_Wlo + wo1, 0, tid);   // next t's P1 chunk0
        }
        group_sync(&g_tile_ctr[80 + t16], (unsigned)(t + 1) * 8u);
        group_reduce<8>(t16, s8, tid, p.bs + 5 * Hd, nullptr, 3, hout, Hd, g_out23, g_out45);
        grid_barrier(++bar);
    }

    // drain the dangling P1 prefetch before reusing smem for the final GEMM
    cp_wait<0>();
    __syncthreads();

    // ---- final: logits = h_final @ W_out^T + b_out  [64, 50000]  (fp32) ----
    {
        float (*As)[TM][ASf]  = (float (*)[TM][ASf])b0;
        float (*Wsm)[TN][WSf] = (float (*)[TN][WSf])(b0 + 2 * TM * ASf * 4);
        const float* hf = gh1;   // (126+1)&1 == 1
        const int ntiles = (Cc + TN - 1) / TN;
        const int mt = (tid >> 4) * 4;
        const int c  = tid & 15;
        float vals[4][4];
        for (int tile = bid; tile < ntiles; tile += GRID) {
            gemm64_f32<Hd>(hf, Hd, p.W_out, tile * 64, Cc, As, Wsm, tid, vals);
            #pragma unroll
            for (int i = 0; i < 4; i++)
                #pragma unroll
                for (int j = 0; j < 4; j++) {
                    const int ng = tile * 64 + c + 16 * j;
                    if (ng < Cc)
                        p.out[(size_t)(mt + i) * Cc + ng] = vals[i][j] + __ldg(&p.b_out[ng]);
                }
        }
    }

    // exit handshake: last CTA resets all sync state for the next graph replay
    __threadfence();
    __syncthreads();
    if (tid == 0) {
        unsigned prev = atomicAdd(&g_exit_cnt, 1u);
        if (prev == GRID - 1u) {
            for (int i = 0; i < 96; i++) g_tile_ctr[i] = 0u;
            g_bar_cnt  = 0u;
            g_bar_gen  = 0u;
            g_exit_cnt = 0u;
            __threadfence();
        }
    }
}

extern "C" void kernel_launch(void* const* d_in, const int* in_sizes, int n_in,
                              void* d_out, int out_size) {
    (void)in_sizes; (void)n_in; (void)out_size;
    PArgs p;
    p.wv      = (const float*)d_in[0];
    p.h       = (const float*)d_in[1];
    p.bi      = (const int*)  d_in[2];
    p.W0      = (const float*)d_in[3];
    p.b0      = (const float*)d_in[4];
    p.Ws      = (const float*)d_in[5];
    p.bs      = (const float*)d_in[6];
    p.W_out   = (const float*)d_in[7];
    p.b_out   = (const float*)d_in[8];
    p.W_sum   = (const float*)d_in[9];
    p.b_sum   = (const float*)d_in[10];
    p.actions = (const float*)d_in[11];
    p.out     = (float*)d_out;

    cudaFuncSetAttribute(rnn_persistent, cudaFuncAttributeMaxDynamicSharedMemorySize, SMEMB);
    cudaFuncSetAttribute(rnn_persistent, cudaFuncAttributePreferredSharedMemoryCarveout, 100);
    rnn_persistent<<<GRID, 256, SMEMB>>>(p);
}